// round 1
// baseline (speedup 1.0000x reference)
#include <cuda_runtime.h>

// Pairwise Jensen-Shannon divergence (in bits):
//   out[i,j] = sum_d [ 0.5*a*lg2(a) + 0.5*b*lg2(b) - m*lg2(m) ],  m = (a+b)/2
// Computed directly in log2 so the final /ln2 is free, and in per-element
// difference form so the accumulator stays small and well-conditioned.

static constexpr int Dc = 512;   // feature dim (fixed by problem)
static constexpr int TM = 64;    // output tile rows  per block
static constexpr int TN = 64;    // output tile cols  per block
static constexpr int KB = 32;    // K-chunk staged in smem
static constexpr int LDPAD = 66; // row stride (float2) -> 528B = 33*16, keeps
                                 // float4 alignment and breaks the d*64 bank pattern

__global__ __launch_bounds__(256, 2)
void jsd_kernel(const float* __restrict__ A, const float* __restrict__ B,
                float* __restrict__ out, int M) {
    // As[d][r] = (0.5*a, 0.5*a*log2(a)) for row (i0+r), feature (k0+d)
    __shared__ float2 As[KB][LDPAD];
    __shared__ float2 Bs[KB][LDPAD];

    const int tid = threadIdx.x;
    const int tx = tid & 15;       // 16 threads across N-tile cols
    const int ty = tid >> 4;       // 16 threads across M-tile rows
    const int i0 = blockIdx.y * TM;
    const int j0 = blockIdx.x * TN;

    float acc[4][4];
#pragma unroll
    for (int u = 0; u < 4; ++u)
#pragma unroll
        for (int v = 0; v < 4; ++v) acc[u][v] = 0.0f;

    for (int k0 = 0; k0 < Dc; k0 += KB) {
        // ---- stage A tile: 64 rows x 32 features, coalesced along d ----
#pragma unroll
        for (int e = 0; e < TM * KB; e += 256) {
            int idx = e + tid;
            int r = idx >> 5;        // row in tile   (KB==32)
            int d = idx & 31;        // feature in chunk
            float v  = A[(size_t)(i0 + r) * Dc + (k0 + d)];
            float lg = __log2f(v);
            float vh = 0.5f * v;
            As[d][r] = make_float2(vh, vh * lg);
        }
        // ---- stage B tile ----
#pragma unroll
        for (int e = 0; e < TN * KB; e += 256) {
            int idx = e + tid;
            int r = idx >> 5;
            int d = idx & 31;
            float v  = B[(size_t)(j0 + r) * Dc + (k0 + d)];
            float lg = __log2f(v);
            float vh = 0.5f * v;
            Bs[d][r] = make_float2(vh, vh * lg);
        }
        __syncthreads();

        // ---- inner: 16 midpoint logs per thread per d (MUFU-bound) ----
#pragma unroll 2
        for (int d = 0; d < KB; ++d) {
            float4 a01 = *reinterpret_cast<const float4*>(&As[d][ty * 4]);
            float4 a23 = *reinterpret_cast<const float4*>(&As[d][ty * 4 + 2]);
            float4 b01 = *reinterpret_cast<const float4*>(&Bs[d][tx * 4]);
            float4 b23 = *reinterpret_cast<const float4*>(&Bs[d][tx * 4 + 2]);
            float ax[4] = {a01.x, a01.z, a23.x, a23.z};
            float ay[4] = {a01.y, a01.w, a23.y, a23.w};
            float bx[4] = {b01.x, b01.z, b23.x, b23.z};
            float by[4] = {b01.y, b01.w, b23.y, b23.w};
#pragma unroll
            for (int u = 0; u < 4; ++u)
#pragma unroll
                for (int v = 0; v < 4; ++v) {
                    float m  = ax[u] + bx[v];           // midpoint (x2 scale folded: already halves)
                    float s  = ay[u] + by[v];           // 0.5 a lg a + 0.5 b lg b
                    float lg = __log2f(m);              // MUFU.LG2
                    acc[u][v] += __fmaf_rn(-m, lg, s);  // += s - m*lg2(m)  (>= 0)
                }
        }
        __syncthreads();
    }

    // ---- store 4x4 micro-tile as float4 rows (coalesced) ----
#pragma unroll
    for (int u = 0; u < 4; ++u) {
        float4 o = make_float4(acc[u][0], acc[u][1], acc[u][2], acc[u][3]);
        *reinterpret_cast<float4*>(
            &out[(size_t)(i0 + ty * 4 + u) * M + (j0 + tx * 4)]) = o;
    }
}

extern "C" void kernel_launch(void* const* d_in, const int* in_sizes, int n_in,
                              void* d_out, int out_size) {
    const float* A = (const float*)d_in[0];
    const float* B = (const float*)d_in[1];
    float* out = (float*)d_out;
    const int N = in_sizes[0] / Dc;   // 1024
    const int M = in_sizes[1] / Dc;   // 1024
    dim3 grid(M / TN, N / TM);        // 16 x 16 blocks
    jsd_kernel<<<grid, 256>>>(A, B, out, M);
}